// round 5
// baseline (speedup 1.0000x reference)
#include <cuda_runtime.h>

#define NN 1024
#define NB 8

typedef unsigned long long u64;

// ---------------- scratch (static device globals: allowed) ----------------
static __device__ float  g_S[512 * NN];   // per-block column-sum slabs (2 MB)
static __device__ float  g_R[NB * NN];    // row sums of Tref per batch
static __device__ float2 g_sf[NN];        // 1.5 * shift factor per element j
static __device__ float2 g_twtab[32 * 32];// twtab[c*32+lane] = exp(-2pi i lane c/1024)
static __device__ float  g_ctm[NN];       // column sums of spectrogram
static __device__ double g_smm;           // sum(Tmeas^2)
static __device__ int    g_maxbits;       // max(Tmeas) as int bits (values >= 0)
static __device__ double g_num[NB], g_smt[NB], g_stt[NB], g_den[NB];

// 5-bit bit reversal of a compile-time-constant p
#define BR5(p) ((((p)&1)<<4)|(((p)&2)<<2)|((p)&4)|(((p)&8)>>2)|(((p)&16)>>4))

// ---------------- packed f32x2 primitives ----------------
__device__ __forceinline__ u64 F2ADD(u64 a, u64 b) {
  u64 r; asm("add.rn.f32x2 %0,%1,%2;" : "=l"(r) : "l"(a), "l"(b)); return r;
}
__device__ __forceinline__ u64 F2MUL(u64 a, u64 b) {
  u64 r; asm("mul.rn.f32x2 %0,%1,%2;" : "=l"(r) : "l"(a), "l"(b)); return r;
}
__device__ __forceinline__ u64 F2FMA(u64 a, u64 b, u64 c) {
  u64 r; asm("fma.rn.f32x2 %0,%1,%2,%3;" : "=l"(r) : "l"(a), "l"(b), "l"(c)); return r;
}
__device__ __forceinline__ u64 PACK2(float lo, float hi) {
  u64 r; asm("mov.b64 %0,{%1,%2};" : "=l"(r) : "f"(lo), "f"(hi)); return r;
}
__device__ __forceinline__ float2 UNPK(u64 v) {
  float2 p; asm("mov.b64 {%0,%1},%2;" : "=f"(p.x), "=f"(p.y) : "l"(v)); return p;
}
#define DUP2(v) PACK2((v), (v))

// ---------------- packed dual-row FFT32 (DIF, natural in, BR out) ----------
// sub via fma(b, -1pack, a): exact, bit-identical to scalar subtract
#define PSUB(a,b) F2FMA((b), kN1, (a))
#define PBF1(i0,i1) { u64 ax=X[i0],ay=Y[i0],bx=X[i1],by=Y[i1];          \
  X[i0]=F2ADD(ax,bx); Y[i0]=F2ADD(ay,by);                               \
  X[i1]=PSUB(ax,bx);  Y[i1]=PSUB(ay,by); }
#define PBFI(i0,i1) { u64 ax=X[i0],ay=Y[i0],bx=X[i1],by=Y[i1];          \
  X[i0]=F2ADD(ax,bx); Y[i0]=F2ADD(ay,by);                               \
  u64 dx=PSUB(ax,bx), dy=PSUB(ay,by);                                   \
  X[i1]=dy; Y[i1]=F2MUL(dx,kN1); }
#define PBF(i0,i1,C,S) { u64 ax=X[i0],ay=Y[i0],bx=X[i1],by=Y[i1];       \
  X[i0]=F2ADD(ax,bx); Y[i0]=F2ADD(ay,by);                               \
  u64 dx=PSUB(ax,bx), dy=PSUB(ay,by);                                   \
  u64 cc=DUP2(C), ss=DUP2(S), sn=DUP2(-(S));                            \
  X[i1]=F2FMA(dy,ss,F2MUL(dx,cc));                                      \
  Y[i1]=F2FMA(dx,sn,F2MUL(dy,cc)); }

__device__ __forceinline__ void fft32p(u64 X[32], u64 Y[32]) {
  const u64 kN1 = DUP2(-1.0f);
  PBF1(0,16)
  PBF(1,17, 0.98078528040323043f, 0.19509032201612825f)
  PBF(2,18, 0.92387953251128674f, 0.38268343236508978f)
  PBF(3,19, 0.83146961230254524f, 0.55557023301960218f)
  PBF(4,20, 0.70710678118654757f, 0.70710678118654757f)
  PBF(5,21, 0.55557023301960218f, 0.83146961230254524f)
  PBF(6,22, 0.38268343236508978f, 0.92387953251128674f)
  PBF(7,23, 0.19509032201612825f, 0.98078528040323043f)
  PBFI(8,24)
  PBF(9,25, -0.19509032201612825f, 0.98078528040323043f)
  PBF(10,26,-0.38268343236508978f, 0.92387953251128674f)
  PBF(11,27,-0.55557023301960218f, 0.83146961230254524f)
  PBF(12,28,-0.70710678118654757f, 0.70710678118654757f)
  PBF(13,29,-0.83146961230254524f, 0.55557023301960218f)
  PBF(14,30,-0.92387953251128674f, 0.38268343236508978f)
  PBF(15,31,-0.98078528040323043f, 0.19509032201612825f)
#pragma unroll
  for (int g = 0; g < 32; g += 16) {
    PBF1(g+0, g+8)
    PBF(g+1, g+9,  0.92387953251128674f, 0.38268343236508978f)
    PBF(g+2, g+10, 0.70710678118654757f, 0.70710678118654757f)
    PBF(g+3, g+11, 0.38268343236508978f, 0.92387953251128674f)
    PBFI(g+4, g+12)
    PBF(g+5, g+13,-0.38268343236508978f, 0.92387953251128674f)
    PBF(g+6, g+14,-0.70710678118654757f, 0.70710678118654757f)
    PBF(g+7, g+15,-0.92387953251128674f, 0.38268343236508978f)
  }
#pragma unroll
  for (int g = 0; g < 32; g += 8) {
    PBF1(g+0, g+4)
    PBF(g+1, g+5,  0.70710678118654757f, 0.70710678118654757f)
    PBFI(g+2, g+6)
    PBF(g+3, g+7, -0.70710678118654757f, 0.70710678118654757f)
  }
#pragma unroll
  for (int g = 0; g < 32; g += 4) {
    PBF1(g+0, g+2)
    PBFI(g+1, g+3)
  }
#pragma unroll
  for (int g = 0; g < 32; g += 2) {
    PBF1(g, g+1)
  }
}

__device__ __forceinline__ float fsqrt_approx(float x) {
  float r;
  asm("sqrt.approx.f32 %0, %1;" : "=f"(r) : "f"(x));
  return r;
}

// ---------------- setup: tables + zero accumulators ----------------
__global__ void k_setup() {
  int gid = blockIdx.x * 256 + threadIdx.x;
  if (gid >= NN) return;
  const float c32 = (float)(2.0 * 337.927 * 1.5);   // fl32(1013.781)
  float t = c32 * (float)(gid - NN / 2);            // fp32 product (as jnp does)
  double s, c;
  sincos((double)t, &s, &c);
  g_sf[gid] = make_float2((float)(1.5 * c), (float)(-1.5 * s));
  {
    int ci = gid >> 5, lane = gid & 31;
    double th = (double)(ci * lane) * (6.283185307179586232e0 / 1024.0);
    double s2, c2;
    sincos(th, &s2, &c2);
    g_twtab[gid] = make_float2((float)c2, (float)(-s2));
  }
  g_ctm[gid] = 0.0f;
  if (gid < NB) { g_num[gid] = 0.0; g_smt[gid] = 0.0; g_stt[gid] = 0.0; g_den[gid] = 0.0; }
  if (gid == 0) { g_smm = 0.0; g_maxbits = 0; }
}

// ---------------- spectrogram stats: colsums, sum of squares, max ----------
__global__ void k_stats(const float* __restrict__ tm) {
  int tid = threadIdx.x;
  int r0 = blockIdx.x * 4;
  float c0 = 0.f, c1 = 0.f, c2 = 0.f, c3 = 0.f;
  float sq = 0.f, mx = 0.f;
#pragma unroll
  for (int r = r0; r < r0 + 4; ++r) {
    const float* rowp = tm + (size_t)r * NN;
    float v0 = rowp[tid];       float v1 = rowp[tid + 256];
    float v2 = rowp[tid + 512]; float v3 = rowp[tid + 768];
    c0 += v0; c1 += v1; c2 += v2; c3 += v3;
    sq = fmaf(v0, v0, sq); sq = fmaf(v1, v1, sq);
    sq = fmaf(v2, v2, sq); sq = fmaf(v3, v3, sq);
    mx = fmaxf(mx, fmaxf(fmaxf(v0, v1), fmaxf(v2, v3)));
  }
  atomicAdd(&g_ctm[tid      ], c0);
  atomicAdd(&g_ctm[tid + 256], c1);
  atomicAdd(&g_ctm[tid + 512], c2);
  atomicAdd(&g_ctm[tid + 768], c3);
#pragma unroll
  for (int o = 16; o; o >>= 1) {
    sq += __shfl_xor_sync(0xffffffffu, sq, o);
    mx = fmaxf(mx, __shfl_xor_sync(0xffffffffu, mx, o));
  }
  __shared__ float ssq[8], smx[8];
  int w = tid >> 5, l = tid & 31;
  if (l == 0) { ssq[w] = sq; smx[w] = mx; }
  __syncthreads();
  if (tid == 0) {
    float a = 0.f, b = 0.f;
#pragma unroll
    for (int i = 0; i < 8; ++i) { a += ssq[i]; b = fmaxf(b, smx[i]); }
    atomicAdd(&g_smm, (double)a);
    atomicMax(&g_maxbits, __float_as_int(b));
  }
}

// ---- main: 4 rows per warp as 2 packed pairs; dual-row f32x2 FFT ---------
__global__ void __launch_bounds__(128) k_main(const float* __restrict__ pred,
                                              const float* __restrict__ tmeas) {
  __shared__ float2 sy2[NN];              // batch analytic signal, interleaved
  __shared__ u64 tbuf[4 * 1056];          // per-warp 32x33 packed transpose buf
  int warp = threadIdx.x >> 5, lane = threadIdx.x & 31;
  int row0 = blockIdx.x * 16 + warp * 4;  // first of 4 rows for this warp
  int b = row0 >> 10;

  for (int i = threadIdx.x; i < NN; i += 128)
    sy2[i] = make_float2(pred[b * 2 * NN + i], pred[b * 2 * NN + NN + i]);
  __syncthreads();

  u64* tb = tbuf + warp * 1056;
  const u64 kN1 = DUP2(-1.0f);

  float csum[32];
#pragma unroll
  for (int p = 0; p < 32; ++p) csum[p] = 0.f;
  float stt = 0.f, smt = 0.f;

#pragma unroll
  for (int t = 0; t < 2; ++t) {
    int m0 = (row0 & (NN - 1)) + 2 * t;   // rows m0, m0+1 packed
    int d0 = m0 - NN / 2;

    u64 X[32], Y[32];
    // prod[j] = 1.5 * y[j] * y[(j-delay)&1023] * sf[j], packed over 2 rows
#pragma unroll
    for (int a = 0; a < 32; ++a) {
      int j = a * 32 + lane;
      int j0 = (j - d0) & (NN - 1);
      int j1 = (j - d0 - 1) & (NN - 1);
      float2 ya = sy2[j];
      float2 b0 = sy2[j0];
      float2 b1 = sy2[j1];
      float2 sf = g_sf[j];
      u64 yax = DUP2(ya.x), yay = DUP2(ya.y), yayn = DUP2(-ya.y);
      u64 ybx = PACK2(b0.x, b1.x), yby = PACK2(b0.y, b1.y);
      u64 sfx = DUP2(sf.x), sfy = DUP2(sf.y), sfyn = DUP2(-sf.y);
      u64 prr = F2FMA(yayn, yby, F2MUL(yax, ybx));
      u64 pri = F2FMA(yay,  ybx, F2MUL(yax, yby));
      X[a] = F2FMA(pri, sfyn, F2MUL(prr, sfx));
      Y[a] = F2FMA(pri, sfx,  F2MUL(prr, sfy));
    }
    // step 1: FFT32 over a  ->  reg p holds Y[BR5(p), col=lane]
    fft32p(X, Y);

    // step 2: twiddle by exp(-2*pi*i * lane * c / 1024), c = BR5(p)
#pragma unroll
    for (int c = 0; c < 32; ++c) {
      int p = BR5(c);
      float2 w = g_twtab[c * 32 + lane];
      u64 wr = DUP2(w.x), wi = DUP2(w.y), win = DUP2(-w.y);
      u64 x = X[p], y = Y[p];
      X[p] = F2FMA(y, win, F2MUL(x, wr));
      Y[p] = F2FMA(y, wr,  F2MUL(x, wi));
    }

    // transpose via padded shared, packed u64, two passes (X then Y)
#pragma unroll
    for (int p = 0; p < 32; ++p) tb[BR5(p) * 33 + lane] = X[p];
    __syncwarp();
#pragma unroll
    for (int bb = 0; bb < 32; ++bb) X[bb] = tb[lane * 33 + bb];
    __syncwarp();
#pragma unroll
    for (int p = 0; p < 32; ++p) tb[BR5(p) * 33 + lane] = Y[p];
    __syncwarp();
#pragma unroll
    for (int bb = 0; bb < 32; ++bb) Y[bb] = tb[lane * 33 + bb];
    __syncwarp();

    // step 3: FFT32 over b -> reg p holds Xf[lane + 32*BR5(p)]
    fft32p(X, Y);

    // Tref[m][col] = |Xf|, col = lane + ((BR5(p)^16)<<5)
    float rsum0 = 0.f, rsum1 = 0.f;
    const float* tmr0 = tmeas + (size_t)m0 * NN;
    const float* tmr1 = tmr0 + NN;
#pragma unroll
    for (int p = 0; p < 32; ++p) {
      int col = lane + ((BR5(p) ^ 16) << 5);
      float2 xs = UNPK(X[p]), ys = UNPK(Y[p]);
      float m0v = fsqrt_approx(fmaf(xs.x, xs.x, ys.x * ys.x));
      float m1v = fsqrt_approx(fmaf(xs.y, xs.y, ys.y * ys.y));
      csum[p] += m0v + m1v;
      rsum0 += m0v; rsum1 += m1v;
      stt = fmaf(m0v, m0v, stt); stt = fmaf(m1v, m1v, stt);
      smt = fmaf(tmr0[col], m0v, smt); smt = fmaf(tmr1[col], m1v, smt);
    }
#pragma unroll
    for (int o = 16; o; o >>= 1) {
      rsum0 += __shfl_xor_sync(0xffffffffu, rsum0, o);
      rsum1 += __shfl_xor_sync(0xffffffffu, rsum1, o);
    }
    if (lane == 0) {
      g_R[row0 + 2 * t    ] = rsum0;
      g_R[row0 + 2 * t + 1] = rsum1;
    }
  }

#pragma unroll
  for (int o = 16; o; o >>= 1) {
    stt += __shfl_xor_sync(0xffffffffu, stt, o);
    smt += __shfl_xor_sync(0xffffffffu, smt, o);
  }
  if (lane == 0) {
    atomicAdd(&g_smt[b], (double)smt);
    atomicAdd(&g_stt[b], (double)stt);
  }

  // combine 4 warps' column sums -> one slab per block (no atomics)
  __syncthreads();                        // all warps done with transpose bufs
  float* sflat = (float*)tbuf;            // need 4096 floats, have 8448
#pragma unroll
  for (int p = 0; p < 32; ++p) {
    int col = lane + ((BR5(p) ^ 16) << 5);
    sflat[warp * 1024 + col] = csum[p];
  }
  __syncthreads();
  float* slab = g_S + (size_t)blockIdx.x * NN;
#pragma unroll
  for (int k = 0; k < 8; ++k) {
    int col = threadIdx.x + 128 * k;
    slab[col] = sflat[col] + sflat[1024 + col] + sflat[2048 + col] + sflat[3072 + col];
  }
}

// ---- den[b] = sum over slabs of dot(slab, R[b]);  num[b] = dot(ctm, R[b]) -
__global__ void k_red() {
  int i = blockIdx.x;                     // 512 blocks: one slab each
  int b = i >> 6;
  int tid = threadIdx.x;                  // 256 threads
  const float* Rp = g_R + b * NN;
  const float* slab = g_S + (size_t)i * NN;

  float r0 = Rp[tid], r1 = Rp[tid + 256], r2 = Rp[tid + 512], r3 = Rp[tid + 768];
  float sden = slab[tid] * r0;
  sden = fmaf(slab[tid + 256], r1, sden);
  sden = fmaf(slab[tid + 512], r2, sden);
  sden = fmaf(slab[tid + 768], r3, sden);
  float snum = 0.f;
  if ((i & 63) == 0) {
    snum = g_ctm[tid] * r0 + g_ctm[tid + 256] * r1
         + g_ctm[tid + 512] * r2 + g_ctm[tid + 768] * r3;
  }
#pragma unroll
  for (int o = 16; o; o >>= 1) {
    sden += __shfl_xor_sync(0xffffffffu, sden, o);
    snum += __shfl_xor_sync(0xffffffffu, snum, o);
  }
  __shared__ float wd[8], wn[8];
  int w = tid >> 5, l = tid & 31;
  if (l == 0) { wd[w] = sden; wn[w] = snum; }
  __syncthreads();
  if (tid == 0) {
    float a = 0.f, c = 0.f;
#pragma unroll
    for (int j = 0; j < 8; ++j) { a += wd[j]; c += wn[j]; }
    atomicAdd(&g_den[b], (double)a);
    if ((i & 63) == 0) atomicAdd(&g_num[b], (double)c);
  }
}

// ---------------- finalize scalar ----------------
__global__ void k_final(float* __restrict__ out) {
  if (threadIdx.x == 0 && blockIdx.x == 0) {
    float mx = __int_as_float(g_maxbits);
    double norm = 1048576.0 * (double)mx * (double)mx;
    double acc = 0.0;
#pragma unroll
    for (int b = 0; b < NB; ++b) {
      double mu = g_num[b] / g_den[b];
      double r = g_smm - 2.0 * mu * g_smt[b] + mu * mu * g_stt[b];
      if (r < 0.0) r = 0.0;
      acc += sqrt(r / norm);
    }
    out[0] = (float)(acc / (double)NB);
  }
}

extern "C" void kernel_launch(void* const* d_in, const int* in_sizes, int n_in,
                              void* d_out, int out_size) {
  const float* pred  = (const float*)d_in[0];   // [8, 2048]
  // d_in[1] = label, unused by the reference loss
  const float* tmeas = (const float*)d_in[2];   // [1024, 1024]
  (void)in_sizes; (void)n_in; (void)out_size;

  k_setup<<<4, 256>>>();
  k_stats<<<256, 256>>>(tmeas);
  k_main<<<512, 128>>>(pred, tmeas);
  k_red<<<512, 256>>>();
  k_final<<<1, 32>>>((float*)d_out);
}